// round 2
// baseline (speedup 1.0000x reference)
#include <cuda_runtime.h>

// ---------------------------------------------------------------------------
// DNN_SKalmanNet_GSS — single persistent kernel, software grid barriers.
// HBM-bound (~499 MB fp32 weights streamed once). Phases:
//   P1: build inputs in smem + l1/l3 GEMV (relu)          [~46 MB]
//   P2: GRU gi/gh GEMV, 4 byte-weighted segments          [~352 MB]
//   G : GRU gate combine (once, chip-wide)                [trivial]
//   P3: l2_W1/l4_W1 GEMV (relu)                           [~67 MB]
//   P4: l2_W2/l4_W2 GEMV -> d_out                         [~34 MB]
// ---------------------------------------------------------------------------

#define H1   5120
#define H2   4096
#define HID  2048
#define IN1  1120

// Scratch (device globals: allocation-free)
__device__ float g_l1[H1];
__device__ float g_l3[H1];
__device__ float g_gi1[3 * HID];
__device__ float g_gh1[3 * HID];
__device__ float g_gi2[3 * HID];
__device__ float g_gh2[3 * HID];
__device__ float g_h1[HID];
__device__ float g_h2[HID];
__device__ float g_hid1[H2];
__device__ float g_hid2[H2];

// Barrier state (self-resetting; zero-init; gen monotonic across replays)
__device__ unsigned int g_bar_cnt;
__device__ unsigned int g_bar_gen;

struct Params {
    const float *si, *oi, *ds, *dob, *le, *J;
    const float *l1W, *l1b, *g1Wih, *g1Whh, *g1bih, *g1bhh;
    const float *l2W1, *l2b1, *l2W2, *l2b2;
    const float *l3W, *l3b, *g2Wih, *g2Whh, *g2bih, *g2bhh;
    const float *l4W1, *l4b1, *l4W2, *l4b2;
    const float *hn1, *hn2;
    float* out;
    int nblk;
    int p2s1, p2s2, p2s3;   // phase-2 segment block boundaries
};

__device__ __forceinline__ void grid_bar(int nblk) {
    __syncthreads();
    if (threadIdx.x == 0) {
        unsigned gen = *(volatile unsigned*)&g_bar_gen;
        __threadfence();                       // publish this block's writes
        unsigned old = atomicAdd(&g_bar_cnt, 1u);
        if (old == (unsigned)nblk - 1u) {
            g_bar_cnt = 0u;                    // reset for next barrier
            __threadfence();
            *(volatile unsigned*)&g_bar_gen = gen + 1u;   // release
        } else {
            while (*(volatile unsigned*)&g_bar_gen == gen) {
                __nanosleep(64);
            }
        }
        __threadfence();                       // acquire other blocks' writes
    }
    __syncthreads();
}

// Warp-per-row GEMV over one segment; x already staged in smem as float4.
__device__ __forceinline__ void gemv_seg(const float* __restrict__ W,
                                         const float* __restrict__ b,
                                         float* __restrict__ y,
                                         int rows, int c4, int act,
                                         int blkRank, int nblkSeg,
                                         const float4* __restrict__ sx) {
    const int wpb  = blockDim.x >> 5;
    const int nw   = nblkSeg * wpb;
    const int lane = threadIdx.x & 31;
    int w = blkRank * wpb + (threadIdx.x >> 5);
    for (int row = w; row < rows; row += nw) {
        const float4* __restrict__ Wr = (const float4*)W + (size_t)row * c4;
        float acc = 0.f;
        #pragma unroll 4
        for (int j = lane; j < c4; j += 32) {
            float4 wv = __ldcs(Wr + j);        // streaming: read-once weights
            float4 xv = sx[j];
            acc = fmaf(wv.x, xv.x, acc);
            acc = fmaf(wv.y, xv.y, acc);
            acc = fmaf(wv.z, xv.z, acc);
            acc = fmaf(wv.w, xv.w, acc);
        }
        #pragma unroll
        for (int o = 16; o; o >>= 1) acc += __shfl_xor_sync(0xffffffffu, acc, o);
        if (lane == 0) {
            float v = acc + b[row];
            if (act) v = fmaxf(v, 0.f);
            y[row] = v;
        }
    }
}

__device__ __forceinline__ void stage(const float* __restrict__ x, int n4,
                                      float4* __restrict__ sx) {
    __syncthreads();
    const float4* __restrict__ xv = (const float4*)x;
    for (int j = threadIdx.x; j < n4; j += blockDim.x) sx[j] = xv[j];
    __syncthreads();
}

extern __shared__ float4 smem_x[];

__global__ __launch_bounds__(256, 2) void skn_kernel(Params p) {
    const int blk  = blockIdx.x;
    const int half = p.nblk >> 1;

    // ---- Phase 1: build input in smem, l1/l3 GEMV (relu) ----
    {
        int seg     = (blk >= half) ? 1 : 0;
        int blkRank = seg ? blk - half : blk;
        int nb      = seg ? p.nblk - half : half;
        float* s = (float*)smem_x;
        for (int i = threadIdx.x; i < IN1; i += blockDim.x) {
            float v;
            if (i < 32)       v = seg ? p.oi[i]       : p.si[i];
            else if (i < 64)  v = seg ? p.dob[i - 32] : p.ds[i - 32];
            else if (i < 96)  v = p.le[i - 64];
            else              v = p.J[i - 96];
            s[i] = v;
        }
        __syncthreads();
        gemv_seg(seg ? p.l3W : p.l1W, seg ? p.l3b : p.l1b,
                 seg ? g_l3 : g_l1, H1, IN1 / 4, 1, blkRank, nb, smem_x);
    }
    grid_bar(p.nblk);

    // ---- Phase 2: GRU pre-gates, 4 byte-weighted segments ----
    {
        const float *W, *xx, *b; float* y; int cols, start, nb;
        if (blk < p.p2s1)      { W = p.g1Wih; xx = g_l1;  b = p.g1bih; y = g_gi1; cols = H1;  start = 0;      nb = p.p2s1;          }
        else if (blk < p.p2s2) { W = p.g1Whh; xx = p.hn1; b = p.g1bhh; y = g_gh1; cols = HID; start = p.p2s1; nb = p.p2s2 - p.p2s1; }
        else if (blk < p.p2s3) { W = p.g2Wih; xx = g_l3;  b = p.g2bih; y = g_gi2; cols = H1;  start = p.p2s2; nb = p.p2s3 - p.p2s2; }
        else                   { W = p.g2Whh; xx = p.hn2; b = p.g2bhh; y = g_gh2; cols = HID; start = p.p2s3; nb = p.nblk - p.p2s3; }
        stage(xx, cols / 4, smem_x);
        gemv_seg(W, b, y, 3 * HID, cols / 4, 0, blk - start, nb, smem_x);
    }
    grid_bar(p.nblk);

    // ---- Gate: h = (1-z)*n + z*h_prev (both branches, once chip-wide) ----
    {
        int i = blk * blockDim.x + threadIdx.x;
        if (i < 2 * HID) {
            int br = (i >= HID);
            int k  = i - br * HID;
            const float* gi = br ? g_gi2 : g_gi1;
            const float* gh = br ? g_gh2 : g_gh1;
            const float* hp = br ? p.hn2 : p.hn1;
            float*       h  = br ? g_h2  : g_h1;
            float r = 1.f / (1.f + __expf(-(gi[k]       + gh[k])));
            float z = 1.f / (1.f + __expf(-(gi[k + HID] + gh[k + HID])));
            float n = tanhf(gi[k + 2 * HID] + r * gh[k + 2 * HID]);
            h[k] = (1.f - z) * n + z * hp[k];
        }
    }
    grid_bar(p.nblk);

    // ---- Phase 3: hidden = relu(W1 @ h + b1) ----
    {
        int seg     = (blk >= half) ? 1 : 0;
        int blkRank = seg ? blk - half : blk;
        int nb      = seg ? p.nblk - half : half;
        stage(seg ? g_h2 : g_h1, HID / 4, smem_x);
        gemv_seg(seg ? p.l4W1 : p.l2W1, seg ? p.l4b1 : p.l2b1,
                 seg ? g_hid2 : g_hid1, H2, HID / 4, 1, blkRank, nb, smem_x);
    }
    grid_bar(p.nblk);

    // ---- Phase 4: out = W2 @ hidden + b2 -> d_out ----
    {
        int seg     = (blk >= half) ? 1 : 0;
        int blkRank = seg ? blk - half : blk;
        int nb      = seg ? p.nblk - half : half;
        stage(seg ? g_hid2 : g_hid1, H2 / 4, smem_x);
        gemv_seg(seg ? p.l4W2 : p.l2W2, seg ? p.l4b2 : p.l2b2,
                 p.out + seg * 1024, 1024, H2 / 4, 0, blkRank, nb, smem_x);
    }
}

extern "C" void kernel_launch(void* const* d_in, const int* in_sizes, int n_in,
                              void* d_out, int out_size) {
    Params p;
    p.si    = (const float*)d_in[0];
    p.oi    = (const float*)d_in[1];
    p.ds    = (const float*)d_in[2];
    p.dob   = (const float*)d_in[3];
    p.le    = (const float*)d_in[4];
    p.J     = (const float*)d_in[5];
    p.l1W   = (const float*)d_in[6];
    p.l1b   = (const float*)d_in[7];
    p.g1Wih = (const float*)d_in[8];
    p.g1Whh = (const float*)d_in[9];
    p.g1bih = (const float*)d_in[10];
    p.g1bhh = (const float*)d_in[11];
    p.l2W1  = (const float*)d_in[12];
    p.l2b1  = (const float*)d_in[13];
    p.l2W2  = (const float*)d_in[14];
    p.l2b2  = (const float*)d_in[15];
    p.l3W   = (const float*)d_in[16];
    p.l3b   = (const float*)d_in[17];
    p.g2Wih = (const float*)d_in[18];
    p.g2Whh = (const float*)d_in[19];
    p.g2bih = (const float*)d_in[20];
    p.g2bhh = (const float*)d_in[21];
    p.l4W1  = (const float*)d_in[22];
    p.l4b1  = (const float*)d_in[23];
    p.l4W2  = (const float*)d_in[24];
    p.l4b2  = (const float*)d_in[25];
    p.hn1   = (const float*)d_in[26];
    p.hn2   = (const float*)d_in[27];
    p.out   = (float*)d_out;

    const int smem = (H1 / 4) * (int)sizeof(float4);   // 20480 B (max staged x)

    int dev = 0;
    cudaGetDevice(&dev);
    int numSM = 148;
    cudaDeviceGetAttribute(&numSM, cudaDevAttrMultiProcessorCount, dev);
    int occ = 1;
    cudaOccupancyMaxActiveBlocksPerMultiprocessor(&occ, skn_kernel, 256, smem);
    int bps  = occ < 1 ? 1 : (occ > 2 ? 2 : occ);
    int nblk = bps * numSM;                // all blocks guaranteed co-resident

    p.nblk = nblk;
    // Phase-2 block split proportional to segment bytes (Wih:Whh = 63:25)
    int b0 = (int)((long long)nblk * 63 / 176); if (b0 < 1) b0 = 1;
    int b1 = (int)((long long)nblk * 25 / 176); if (b1 < 1) b1 = 1;
    int b2 = b0;
    p.p2s1 = b0;
    p.p2s2 = b0 + b1;
    p.p2s3 = b0 + b1 + b2;
    if (p.p2s3 >= nblk) p.p2s3 = nblk - 1;   // keep seg3 non-empty

    skn_kernel<<<nblk, 256, smem>>>(p);
    (void)in_sizes; (void)n_in; (void)out_size;
}

// round 3
// speedup vs baseline: 1.0400x; 1.0400x over previous
#include <cuda_runtime.h>

// ---------------------------------------------------------------------------
// DNN_SKalmanNet_GSS — batch-1 GEMV chain, HBM-bound (~499 MB weights/pass).
// 4 launches (R1 structure minus pure-overhead kernels):
//   K1: input built in smem per block + l1/l3 GEMV (relu)        [~46 MB]
//   K2: GRU gi/gh GEMV, 4 segments                               [~352 MB]
//   K3: gate fused into staging (each block computes h in smem)
//       + l2_W1/l4_W1 GEMV (relu)                                [~67 MB]
//   K4: l2_W2/l4_W2 GEMV -> d_out                                [~34 MB]
// ---------------------------------------------------------------------------

#define H1   5120
#define H2   4096
#define HID  2048
#define IN1  1120

// Scratch (device globals: allocation-free)
__device__ float g_l1[H1];
__device__ float g_l3[H1];
__device__ float g_gi1[3 * HID];
__device__ float g_gh1[3 * HID];
__device__ float g_gi2[3 * HID];
__device__ float g_gh2[3 * HID];
__device__ float g_hid1[H2];
__device__ float g_hid2[H2];

// Warp-per-row GEMV; x staged in smem as float4.
__device__ __forceinline__ void gemv_core(const float* __restrict__ W,
                                          const float* __restrict__ b,
                                          float* __restrict__ y,
                                          int rows, int c4, int act,
                                          const float4* __restrict__ sx) {
    const int lane = threadIdx.x & 31;
    const int warp = (blockIdx.x * blockDim.x + threadIdx.x) >> 5;
    const int nw   = (gridDim.x * blockDim.x) >> 5;
    for (int row = warp; row < rows; row += nw) {
        const float4* __restrict__ Wr = (const float4*)W + (size_t)row * c4;
        float acc = 0.f;
        #pragma unroll 4
        for (int j = lane; j < c4; j += 32) {
            float4 wv = __ldcs(Wr + j);           // read-once weights: stream
            float4 xv = sx[j];
            acc = fmaf(wv.x, xv.x, acc);
            acc = fmaf(wv.y, xv.y, acc);
            acc = fmaf(wv.z, xv.z, acc);
            acc = fmaf(wv.w, xv.w, acc);
        }
        #pragma unroll
        for (int o = 16; o; o >>= 1) acc += __shfl_xor_sync(0xffffffffu, acc, o);
        if (lane == 0) {
            float v = acc + b[row];
            if (act) v = fmaxf(v, 0.f);
            y[row] = v;
        }
    }
}

extern __shared__ float4 smem_x[];

// K1: build branch input in smem, then l1/l3 GEMV (relu). blockIdx.y = branch.
__global__ void k1_input_gemv(const float* __restrict__ si,
                              const float* __restrict__ oi,
                              const float* __restrict__ ds,
                              const float* __restrict__ dob,
                              const float* __restrict__ le,
                              const float* __restrict__ J,
                              const float* __restrict__ l1W,
                              const float* __restrict__ l1b,
                              const float* __restrict__ l3W,
                              const float* __restrict__ l3b) {
    const int br = blockIdx.y;
    float* s = (float*)smem_x;
    for (int i = threadIdx.x; i < IN1; i += blockDim.x) {
        float v;
        if (i < 32)       v = br ? oi[i]       : si[i];
        else if (i < 64)  v = br ? dob[i - 32] : ds[i - 32];
        else if (i < 96)  v = le[i - 64];
        else              v = J[i - 96];
        s[i] = v;
    }
    __syncthreads();
    gemv_core(br ? l3W : l1W, br ? l3b : l1b, br ? g_l3 : g_l1,
              H1, IN1 / 4, 1, smem_x);
}

// K2: 4-segment GEMV (gi1, gh1, gi2, gh2). blockIdx.y = segment.
struct Seg { const float *W, *x, *b; float* y; int rows, c4; };
struct Segs4 { Seg s[4]; };

__global__ void k2_gru_gemv(Segs4 segs) {
    Seg s = segs.s[blockIdx.y];
    const float4* __restrict__ xv = (const float4*)s.x;
    for (int j = threadIdx.x; j < s.c4; j += blockDim.x) smem_x[j] = xv[j];
    __syncthreads();
    gemv_core(s.W, s.b, s.y, s.rows, s.c4, 0, smem_x);
}

// K3: each block computes full GRU h (2048) from gi/gh/hn into smem, then
// hidden = relu(W1 @ h + b1). blockIdx.y = branch.
__global__ void k3_gate_gemv(const float* __restrict__ hn1,
                             const float* __restrict__ hn2,
                             const float* __restrict__ l2W1,
                             const float* __restrict__ l2b1,
                             const float* __restrict__ l4W1,
                             const float* __restrict__ l4b1) {
    const int br = blockIdx.y;
    const float* __restrict__ gi = br ? g_gi2 : g_gi1;
    const float* __restrict__ gh = br ? g_gh2 : g_gh1;
    const float* __restrict__ hp = br ? hn2 : hn1;
    float* s = (float*)smem_x;
    for (int k = threadIdx.x; k < HID; k += blockDim.x) {
        float r = 1.f / (1.f + __expf(-(gi[k]       + gh[k])));
        float z = 1.f / (1.f + __expf(-(gi[k + HID] + gh[k + HID])));
        float n = tanhf(gi[k + 2 * HID] + r * gh[k + 2 * HID]);
        s[k] = (1.f - z) * n + z * hp[k];
    }
    __syncthreads();
    gemv_core(br ? l4W1 : l2W1, br ? l4b1 : l2b1, br ? g_hid2 : g_hid1,
              H2, HID / 4, 1, smem_x);
}

// K4: out = W2 @ hidden + b2 -> d_out. blockIdx.y = branch.
__global__ void k4_out_gemv(const float* __restrict__ l2W2,
                            const float* __restrict__ l2b2,
                            const float* __restrict__ l4W2,
                            const float* __restrict__ l4b2,
                            float* __restrict__ out) {
    const int br = blockIdx.y;
    const float* __restrict__ x = br ? g_hid2 : g_hid1;
    const float4* __restrict__ xv = (const float4*)x;
    for (int j = threadIdx.x; j < H2 / 4; j += blockDim.x) smem_x[j] = xv[j];
    __syncthreads();
    gemv_core(br ? l4W2 : l2W2, br ? l4b2 : l2b2, out + br * 1024,
              1024, H2 / 4, 0, smem_x);
}

extern "C" void kernel_launch(void* const* d_in, const int* in_sizes, int n_in,
                              void* d_out, int out_size) {
    const float* si    = (const float*)d_in[0];
    const float* oi    = (const float*)d_in[1];
    const float* ds    = (const float*)d_in[2];
    const float* dob   = (const float*)d_in[3];
    const float* le    = (const float*)d_in[4];
    const float* J     = (const float*)d_in[5];
    const float* l1W   = (const float*)d_in[6];
    const float* l1b   = (const float*)d_in[7];
    const float* g1Wih = (const float*)d_in[8];
    const float* g1Whh = (const float*)d_in[9];
    const float* g1bih = (const float*)d_in[10];
    const float* g1bhh = (const float*)d_in[11];
    const float* l2W1  = (const float*)d_in[12];
    const float* l2b1  = (const float*)d_in[13];
    const float* l2W2  = (const float*)d_in[14];
    const float* l2b2  = (const float*)d_in[15];
    const float* l3W   = (const float*)d_in[16];
    const float* l3b   = (const float*)d_in[17];
    const float* g2Wih = (const float*)d_in[18];
    const float* g2Whh = (const float*)d_in[19];
    const float* g2bih = (const float*)d_in[20];
    const float* g2bhh = (const float*)d_in[21];
    const float* l4W1  = (const float*)d_in[22];
    const float* l4b1  = (const float*)d_in[23];
    const float* l4W2  = (const float*)d_in[24];
    const float* l4b2  = (const float*)d_in[25];
    const float* hn1   = (const float*)d_in[26];
    const float* hn2   = (const float*)d_in[27];
    float* out = (float*)d_out;

    float *p_l1, *p_l3, *p_gi1, *p_gh1, *p_gi2, *p_gh2;
    cudaGetSymbolAddress((void**)&p_l1,  g_l1);
    cudaGetSymbolAddress((void**)&p_l3,  g_l3);
    cudaGetSymbolAddress((void**)&p_gi1, g_gi1);
    cudaGetSymbolAddress((void**)&p_gh1, g_gh1);
    cudaGetSymbolAddress((void**)&p_gi2, g_gi2);
    cudaGetSymbolAddress((void**)&p_gh2, g_gh2);

    // K1: 5120 rows, warp per row -> 640 blocks x 2 branches
    k1_input_gemv<<<dim3(H1 / 8, 2), 256, IN1 * sizeof(float)>>>(
        si, oi, ds, dob, le, J, l1W, l1b, l3W, l3b);

    // K2: 6144 rows x 4 segments -> 768 blocks x 4
    {
        Segs4 sg;
        sg.s[0] = { g1Wih, p_l1, g1bih, p_gi1, 3 * HID, H1 / 4 };
        sg.s[1] = { g1Whh, hn1,  g1bhh, p_gh1, 3 * HID, HID / 4 };
        sg.s[2] = { g2Wih, p_l3, g2bih, p_gi2, 3 * HID, H1 / 4 };
        sg.s[3] = { g2Whh, hn2,  g2bhh, p_gh2, 3 * HID, HID / 4 };
        k2_gru_gemv<<<dim3((3 * HID) / 8, 4), 256, H1 * sizeof(float)>>>(sg);
    }

    // K3: gate fused + 4096 rows -> 512 blocks x 2
    k3_gate_gemv<<<dim3(H2 / 8, 2), 256, HID * sizeof(float)>>>(
        hn1, hn2, l2W1, l2b1, l4W1, l4b1);

    // K4: 1024 rows -> 128 blocks x 2
    k4_out_gemv<<<dim3(1024 / 8, 2), 256, H2 * sizeof(float)>>>(
        l2W2, l2b2, l4W2, l4b2, out);

    (void)in_sizes; (void)n_in; (void)out_size;
}